// round 10
// baseline (speedup 1.0000x reference)
#include <cuda_runtime.h>
#include <cuda_bf16.h>

// Problem dims (fixed)
#define BB 64
#define TT 512
#define EE 512
#define HH 1024
#define OO 512
#define MROWS (BB * TT)   // 32768

// ---------------- packed fp32 FMA (FFMA2) ----------------
__device__ __forceinline__ float2 ffma2(float2 a, float2 b, float2 c) {
    union { float2 f; unsigned long long u; } A, B_, C_, D;
    A.f = a; B_.f = b; C_.f = c;
    asm("fma.rn.f32x2 %0, %1, %2, %3;" : "=l"(D.u) : "l"(A.u), "l"(B_.u), "l"(C_.u));
    return D.f;
}

// ---------------- device scratch (no cudaMalloc allowed) ----------------
__device__ float g_buf0[MROWS * HH];   // XP, then YP         (~134 MB)
__device__ float g_buf1[MROWS * HH];   // H0_all, then H1_all (~134 MB)
// Per-row-group barrier counters, padded to 128 B stride so each lives in its
// own L2 line/LTS slice (no cross-group sector contention or invalidation).
__device__ unsigned g_bar[4 * 32];

__global__ void reset_barrier_kernel() {
    g_bar[0 * 32] = 0u; g_bar[1 * 32] = 0u; g_bar[2 * 32] = 0u; g_bar[3 * 32] = 0u;
}

// ---------------- generic GEMM: C[M,N] = A[M,K] @ W[N,K]^T + bias ----------------
// Tiles: 128x128x16, 256 threads, 8x8 micro-tile with float2 column pairs.
// Register double-buffering: next k-tile LDG issued before current compute.
#define TM 128
#define TN 128
#define TK 16

__global__ __launch_bounds__(256, 2)
void gemm_bias_kernel(const float* __restrict__ A,
                      const float* __restrict__ W,
                      const float* __restrict__ bias,
                      float* __restrict__ C,
                      int M, int N, int K)
{
    __shared__ float As[TK][TM + 4];
    __shared__ float Bs[TK][TN + 4];

    const int bm = blockIdx.y * TM;
    const int bn = blockIdx.x * TN;
    const int tid = threadIdx.x;
    const int ty = tid >> 4;        // 0..15
    const int tx = tid & 15;        // 0..15
    const int row0 = ty * 8;
    const int col0 = tx * 8;

    // staging-load mapping: thread covers rows ri and ri+64 at k-quad kq
    const int ri = tid >> 2;            // 0..63
    const int kq = (tid & 3) * 4;       // 0,4,8,12

    const float* Abase0 = A + (size_t)(bm + ri) * K + kq;
    const float* Abase1 = A + (size_t)(bm + ri + 64) * K + kq;
    const float* Wbase0 = W + (size_t)(bn + ri) * K + kq;
    const float* Wbase1 = W + (size_t)(bn + ri + 64) * K + kq;

    float2 acc[8][4];
#pragma unroll
    for (int r = 0; r < 8; ++r)
#pragma unroll
        for (int p = 0; p < 4; ++p) acc[r][p] = make_float2(0.f, 0.f);

    auto sts_tiles = [&](float4 a0, float4 a1, float4 b0, float4 b1) {
        As[kq + 0][ri] = a0.x; As[kq + 1][ri] = a0.y;
        As[kq + 2][ri] = a0.z; As[kq + 3][ri] = a0.w;
        As[kq + 0][ri + 64] = a1.x; As[kq + 1][ri + 64] = a1.y;
        As[kq + 2][ri + 64] = a1.z; As[kq + 3][ri + 64] = a1.w;
        Bs[kq + 0][ri] = b0.x; Bs[kq + 1][ri] = b0.y;
        Bs[kq + 2][ri] = b0.z; Bs[kq + 3][ri] = b0.w;
        Bs[kq + 0][ri + 64] = b1.x; Bs[kq + 1][ri + 64] = b1.y;
        Bs[kq + 2][ri + 64] = b1.z; Bs[kq + 3][ri + 64] = b1.w;
    };

    auto compute_tile = [&]() {
#pragma unroll
        for (int kk = 0; kk < TK; ++kk) {
            float4 a0 = *reinterpret_cast<const float4*>(&As[kk][row0]);
            float4 a1 = *reinterpret_cast<const float4*>(&As[kk][row0 + 4]);
            float4 b0 = *reinterpret_cast<const float4*>(&Bs[kk][col0]);
            float4 b1 = *reinterpret_cast<const float4*>(&Bs[kk][col0 + 4]);
            float2 bp0 = make_float2(b0.x, b0.y);
            float2 bp1 = make_float2(b0.z, b0.w);
            float2 bp2 = make_float2(b1.x, b1.y);
            float2 bp3 = make_float2(b1.z, b1.w);
            float ar[8] = {a0.x, a0.y, a0.z, a0.w, a1.x, a1.y, a1.z, a1.w};
#pragma unroll
            for (int r = 0; r < 8; ++r) {
                float2 ad = make_float2(ar[r], ar[r]);
                acc[r][0] = ffma2(ad, bp0, acc[r][0]);
                acc[r][1] = ffma2(ad, bp1, acc[r][1]);
                acc[r][2] = ffma2(ad, bp2, acc[r][2]);
                acc[r][3] = ffma2(ad, bp3, acc[r][3]);
            }
        }
    };

    // prologue: tile 0
    float4 a0 = *reinterpret_cast<const float4*>(Abase0);
    float4 a1 = *reinterpret_cast<const float4*>(Abase1);
    float4 b0 = *reinterpret_cast<const float4*>(Wbase0);
    float4 b1 = *reinterpret_cast<const float4*>(Wbase1);
    sts_tiles(a0, a1, b0, b1);
    __syncthreads();

    for (int k0 = TK; k0 < K; k0 += TK) {
        // prefetch next tile into registers (overlaps with compute below)
        a0 = *reinterpret_cast<const float4*>(Abase0 + k0);
        a1 = *reinterpret_cast<const float4*>(Abase1 + k0);
        b0 = *reinterpret_cast<const float4*>(Wbase0 + k0);
        b1 = *reinterpret_cast<const float4*>(Wbase1 + k0);
        compute_tile();
        __syncthreads();
        sts_tiles(a0, a1, b0, b1);
        __syncthreads();
    }
    compute_tile();

    float4 bi0 = *reinterpret_cast<const float4*>(bias + bn + col0);
    float4 bi1 = *reinterpret_cast<const float4*>(bias + bn + col0 + 4);
#pragma unroll
    for (int r = 0; r < 8; ++r) {
        size_t row = (size_t)(bm + row0 + r);
        float4 o0 = make_float4(acc[r][0].x + bi0.x, acc[r][0].y + bi0.y,
                                acc[r][1].x + bi0.z, acc[r][1].y + bi0.w);
        float4 o1 = make_float4(acc[r][2].x + bi1.x, acc[r][2].y + bi1.y,
                                acc[r][3].x + bi1.z, acc[r][3].y + bi1.w);
        *reinterpret_cast<float4*>(C + row * N + bn + col0)     = o0;
        *reinterpret_cast<float4*>(C + row * N + bn + col0 + 4) = o1;
    }
}

// ---------------- persistent recurrent scan ----------------
// Grid: 128 blocks = 4 row-groups (16 batch rows) x 32 col-tiles (32 cols).
// 256 threads/block = 8 warps = 2 warps per SMSP.
//
// k-split: thread group kh = tid>>7 handles k-subrange [kh*64, kh*64+64) of
// each 128-k chunk, so both warps of an SMSP compute concurrently on the same
// staged chunk -> FFMA2 pipe (rt 2/SMSP, floor 4096 cyc/step) stays fed even
// when one warp stalls on LDS/staging. Cross-group reduction via 2 KB smem at
// step end.
//
// h staging is CHUNKED (8 chunks of 128 k) and double-buffered:
//   STS(chunk c); sync; LDG(chunk c+1); FMA(chunk c)
// Staging lane map: lane takes float4 quads {tid&15, (tid&15)+16} of its row
// -> 16 B lane stride: STS.128 conflict-free (lanes 0-7 = 128 B contiguous
// per phase) and LDG fully coalesced (256 B per half-warp). h reads use
// __ldcg (L2, lines shared by 32 blocks); P reads use __ldcs (evict-first,
// each address read exactly once -> don't displace h/W reuse set in L2).
//
// FMA lane mapping (within 128-thread group) r_loc = wtid&15,
// c_loc = (wtid>>4)*4: warp spans 16 rows x 8 cols -> W LDS gets 16-way
// broadcast dedup, keeping crossbar traffic (~3.6k cyc/step incl. staging)
// under the FFMA2 floor.
#define SCAN_BLOCKS 128
#define SCAN_THREADS 256
#define CHUNK 128                         // k per chunk
#define NCHUNK (HH / CHUNK)               // 8
#define CP (CHUNK + 4)                    // padded chunk row
#define SCAN_SMEM ((HH * 32 + 2 * 16 * CP) * (int)sizeof(float))   // 147,968 B

__global__ __launch_bounds__(SCAN_THREADS, 1)
void scan_kernel(const float* __restrict__ P,      // [B][T][H] input proj (incl. its bias)
                 const float* __restrict__ Whh,    // [H][H] row-major (out, in)
                 const float* __restrict__ bias,   // [H]
                 const float* __restrict__ hinit,  // [B][H]
                 float* __restrict__ Hst)          // [B][T][H] states out
{
    extern __shared__ float smem[];
    float* Ws = smem;                     // [HH][32] transposed W slice
    float* hs = smem + HH * 32;           // [2][16][CP] chunk double buffer

    const int tid = threadIdx.x;
    const int bc = (blockIdx.x & 31) * 32;   // column base
    const int rg = blockIdx.x >> 5;          // row group 0..3
    const int br = rg * 16;                  // batch-row base
    unsigned* barp = &g_bar[rg * 32];        // 128 B-strided counter (own L2 line)

    // One-time: load W slice transposed into SMEM (lane c spread -> conflict-free STS)
    for (int i = tid; i < 32 * (HH / 4); i += SCAN_THREADS) {
        int c = i & 31;        // 0..31
        int q = i >> 5;        // 0..255 (float4 index along K)
        float4 v = *reinterpret_cast<const float4*>(Whh + (size_t)(bc + c) * HH + q * 4);
        Ws[(q * 4 + 0) * 32 + c] = v.x;
        Ws[(q * 4 + 1) * 32 + c] = v.y;
        Ws[(q * 4 + 2) * 32 + c] = v.z;
        Ws[(q * 4 + 3) * 32 + c] = v.w;
    }

    const int kh    = tid >> 7;          // k-half group (0 or 1)
    const int wtid  = tid & 127;
    const int khoff = kh * 64;           // k offset within a chunk
    const int r_loc = wtid & 15;         // warp spans all 16 rows
    const int c_loc = (wtid >> 4) * 4;   // 2 col-groups per warp -> W broadcast
    // staging mapping: row st_r, float4 quads {st_q, st_q+16} (16 B lane stride)
    const int st_r = tid >> 4;           // 0..15
    const int st_q = tid & 15;           // 0..15
    const float4 bias4 = *reinterpret_cast<const float4*>(bias + bc + c_loc);
    __syncthreads();

    for (int t = 0; t < TT; ++t) {
        // prefetch this step's input projection early (group 0 only needs it);
        // streaming: each P address is read exactly once whole-kernel.
        size_t off = (size_t)(br + r_loc) * TT * HH + (size_t)t * HH + bc + c_loc;
        float4 pv = make_float4(0.f, 0.f, 0.f, 0.f);
        if (tid < 128) pv = __ldcs(reinterpret_cast<const float4*>(P + off));

        const float* hbase;
        size_t rstride;
        if (t == 0) { hbase = hinit + (size_t)br * HH;                           rstride = HH; }
        else        { hbase = Hst + (size_t)br * TT * HH + (size_t)(t - 1) * HH; rstride = (size_t)TT * HH; }
        const float* hrowg = hbase + (size_t)st_r * rstride;   // this thread's staging row

        // prologue: load chunk 0 into registers (quads st_q and st_q+16)
        float4 st[2];
#pragma unroll
        for (int j = 0; j < 2; ++j)
            st[j] = __ldcg(reinterpret_cast<const float4*>(hrowg) + st_q + j * 16);

        float2 acc[4][2];
#pragma unroll
        for (int j = 0; j < 4; ++j) { acc[j][0] = make_float2(0.f, 0.f); acc[j][1] = make_float2(0.f, 0.f); }

        for (int c = 0; c < NCHUNK; ++c) {
            // commit staged registers to this chunk's buffer (conflict-free STS.128)
            float* buf = hs + (c & 1) * (16 * CP);
#pragma unroll
            for (int j = 0; j < 2; ++j)
                *reinterpret_cast<float4*>(&buf[st_r * CP + (st_q + j * 16) * 4]) = st[j];
            __syncthreads();

            // prefetch next chunk (overlaps the FMA loop below)
            if (c + 1 < NCHUNK) {
#pragma unroll
                for (int j = 0; j < 2; ++j)
                    st[j] = __ldcg(reinterpret_cast<const float4*>(hrowg + (c + 1) * CHUNK) + st_q + j * 16);
            }

            // FMA over this group's 64-k subrange of the chunk
            const float* hrow = &buf[r_loc * CP + khoff];
            const float* wb = Ws + (c * CHUNK + khoff) * 32;
#pragma unroll 4
            for (int k = 0; k < 64; k += 4) {
                float4 hv = *reinterpret_cast<const float4*>(&hrow[k]);
                float hvr[4] = {hv.x, hv.y, hv.z, hv.w};
#pragma unroll
                for (int j = 0; j < 4; ++j) {
                    float4 w = *reinterpret_cast<const float4*>(&wb[(k + j) * 32 + c_loc]);
                    float2 hd = make_float2(hvr[j], hvr[j]);
                    acc[j][0] = ffma2(hd, make_float2(w.x, w.y), acc[j][0]);
                    acc[j][1] = ffma2(hd, make_float2(w.z, w.w), acc[j][1]);
                }
            }
        }

        float s0 = (acc[0][0].x + acc[1][0].x) + (acc[2][0].x + acc[3][0].x);
        float s1 = (acc[0][0].y + acc[1][0].y) + (acc[2][0].y + acc[3][0].y);
        float s2 = (acc[0][1].x + acc[1][1].x) + (acc[2][1].x + acc[3][1].x);
        float s3 = (acc[0][1].y + acc[1][1].y) + (acc[2][1].y + acc[3][1].y);

        // cross-group reduction: group 1 writes partials, group 0 combines.
        // red region = chunk buffer 0; last FMA read buffer 1, and next step's
        // first STS to buffer 0 is behind two syncs + the grid barrier -> safe.
        float* red = hs;
        if (tid >= 128)
            *reinterpret_cast<float4*>(&red[wtid * 4]) = make_float4(s0, s1, s2, s3);
        __syncthreads();
        if (tid < 128) {
            float4 pr = *reinterpret_cast<const float4*>(&red[wtid * 4]);
            float4 ov;
            ov.x = tanhf(s0 + pr.x + pv.x + bias4.x);
            ov.y = tanhf(s1 + pr.y + pv.y + bias4.y);
            ov.z = tanhf(s2 + pr.z + pv.z + bias4.z);
            ov.w = tanhf(s3 + pr.w + pv.w + bias4.w);
            *reinterpret_cast<float4*>(Hst + off) = ov;
        }

        // ---- per-row-group barrier (32 blocks), release/acquire ----
        __syncthreads();
        if (tid == 0) {
            asm volatile("red.release.gpu.global.add.u32 [%0], 1;"
                         :: "l"(barp) : "memory");
            unsigned target = (unsigned)(t + 1) * 32u;
            unsigned v;
            int spins = 0;
            do {
                asm volatile("ld.acquire.gpu.global.u32 %0, [%1];"
                             : "=r"(v) : "l"(barp) : "memory");
                if (v >= target) break;
                if (++spins > 4) __nanosleep(64);   // spin first, then sleep
            } while (true);
        }
        __syncthreads();
    }
}

// ---------------- launch ----------------
extern "C" void kernel_launch(void* const* d_in, const int* in_sizes, int n_in,
                              void* d_out, int out_size)
{
    (void)in_sizes; (void)n_in; (void)out_size;
    const float* emb    = (const float*)d_in[0];   // (B,T,E)
    const float* h0     = (const float*)d_in[1];   // (L,B,H)
    const float* W_ih0  = (const float*)d_in[2];   // (H,E)
    const float* b_ih0  = (const float*)d_in[3];
    const float* W_ih1  = (const float*)d_in[4];   // (H,H)
    const float* b_ih1  = (const float*)d_in[5];
    const float* W_hh0  = (const float*)d_in[6];   // (H,H)
    const float* b_hh0  = (const float*)d_in[7];
    const float* W_hh1  = (const float*)d_in[8];   // (H,H)
    const float* b_hh1  = (const float*)d_in[9];
    const float* W_out  = (const float*)d_in[10];  // (O,H)
    const float* b_out  = (const float*)d_in[11];
    float* out = (float*)d_out;                    // (B,T,O)

    float *buf0, *buf1;
    cudaGetSymbolAddress((void**)&buf0, g_buf0);
    cudaGetSymbolAddress((void**)&buf1, g_buf1);

    cudaFuncSetAttribute(scan_kernel, cudaFuncAttributeMaxDynamicSharedMemorySize, SCAN_SMEM);

    // 1. XP = emb @ W_ih0^T + b_ih0   (row b*T+t matches (B,T,H) layout)
    gemm_bias_kernel<<<dim3(HH / TN, MROWS / TM), 256>>>(emb, W_ih0, b_ih0, buf0, MROWS, HH, EE);

    // 2. layer-0 scan: buf1 = H0_all
    reset_barrier_kernel<<<1, 1>>>();
    scan_kernel<<<SCAN_BLOCKS, SCAN_THREADS, SCAN_SMEM>>>(buf0, W_hh0, b_hh0, h0, buf1);

    // 3. YP = H0_all @ W_ih1^T + b_ih1  (overwrite buf0)
    gemm_bias_kernel<<<dim3(HH / TN, MROWS / TM), 256>>>(buf1, W_ih1, b_ih1, buf0, MROWS, HH, HH);

    // 4. layer-1 scan: buf1 = H1_all (overwrite H0_all)
    reset_barrier_kernel<<<1, 1>>>();
    scan_kernel<<<SCAN_BLOCKS, SCAN_THREADS, SCAN_SMEM>>>(buf0, W_hh1, b_hh1, h0 + BB * HH, buf1);

    // 5. out = H1_all @ W_out^T + b_out   (row b*T+t matches (B,T,O) layout)
    gemm_bias_kernel<<<dim3(OO / TN, MROWS / TM), 256>>>(buf1, W_out, b_out, out, MROWS, OO, HH);
}

// round 13
// speedup vs baseline: 1.0362x; 1.0362x over previous
#include <cuda_runtime.h>
#include <cuda_bf16.h>

// Problem dims (fixed)
#define BB 64
#define TT 512
#define EE 512
#define HH 1024
#define OO 512
#define MROWS (BB * TT)   // 32768

// ---------------- packed fp32 FMA (FFMA2) ----------------
__device__ __forceinline__ float2 ffma2(float2 a, float2 b, float2 c) {
    union { float2 f; unsigned long long u; } A, B_, C_, D;
    A.f = a; B_.f = b; C_.f = c;
    asm("fma.rn.f32x2 %0, %1, %2, %3;" : "=l"(D.u) : "l"(A.u), "l"(B_.u), "l"(C_.u));
    return D.f;
}

// ---------------- device scratch (no cudaMalloc allowed) ----------------
__device__ float g_buf0[MROWS * HH];   // XP, then YP         (~134 MB)
__device__ float g_buf1[MROWS * HH];   // H0_all, then H1_all (~134 MB)
// Per-row-group barrier counters, 128 B stride (own L2 line each).
__device__ unsigned g_bar[4 * 32];

__global__ void reset_barrier_kernel() {
    g_bar[0 * 32] = 0u; g_bar[1 * 32] = 0u; g_bar[2 * 32] = 0u; g_bar[3 * 32] = 0u;
}

// ---------------- generic GEMM: C[M,N] = A[M,K] @ W[N,K]^T + bias ----------------
// Tiles: 128x128x16, 256 threads, 8x8 micro-tile with float2 column pairs.
// Register double-buffering: next k-tile LDG issued before current compute.
//
// R10 post-mortem fix: __launch_bounds__(256,2) forced a 128-reg cap ->
// spills -> L1TEX 93.2% (LDL/STL) and only 24.3% achieved occ (1 CTA/SM
// anyway). (256,1) gives 255 regs: no spills, same resident occupancy.
#define TM 128
#define TN 128
#define TK 16

__global__ __launch_bounds__(256, 1)
void gemm_bias_kernel(const float* __restrict__ A,
                      const float* __restrict__ W,
                      const float* __restrict__ bias,
                      float* __restrict__ C,
                      int M, int N, int K)
{
    __shared__ float As[TK][TM + 4];
    __shared__ float Bs[TK][TN + 4];

    const int bm = blockIdx.y * TM;
    const int bn = blockIdx.x * TN;
    const int tid = threadIdx.x;
    const int ty = tid >> 4;        // 0..15
    const int tx = tid & 15;        // 0..15
    const int row0 = ty * 8;
    const int col0 = tx * 8;

    // staging-load mapping: thread covers rows ri and ri+64 at k-quad kq
    const int ri = tid >> 2;            // 0..63
    const int kq = (tid & 3) * 4;       // 0,4,8,12

    const float* Abase0 = A + (size_t)(bm + ri) * K + kq;
    const float* Abase1 = A + (size_t)(bm + ri + 64) * K + kq;
    const float* Wbase0 = W + (size_t)(bn + ri) * K + kq;
    const float* Wbase1 = W + (size_t)(bn + ri + 64) * K + kq;

    float2 acc[8][4];
#pragma unroll
    for (int r = 0; r < 8; ++r)
#pragma unroll
        for (int p = 0; p < 4; ++p) acc[r][p] = make_float2(0.f, 0.f);

    auto sts_tiles = [&](float4 a0, float4 a1, float4 b0, float4 b1) {
        As[kq + 0][ri] = a0.x; As[kq + 1][ri] = a0.y;
        As[kq + 2][ri] = a0.z; As[kq + 3][ri] = a0.w;
        As[kq + 0][ri + 64] = a1.x; As[kq + 1][ri + 64] = a1.y;
        As[kq + 2][ri + 64] = a1.z; As[kq + 3][ri + 64] = a1.w;
        Bs[kq + 0][ri] = b0.x; Bs[kq + 1][ri] = b0.y;
        Bs[kq + 2][ri] = b0.z; Bs[kq + 3][ri] = b0.w;
        Bs[kq + 0][ri + 64] = b1.x; Bs[kq + 1][ri + 64] = b1.y;
        Bs[kq + 2][ri + 64] = b1.z; Bs[kq + 3][ri + 64] = b1.w;
    };

    auto compute_tile = [&]() {
#pragma unroll
        for (int kk = 0; kk < TK; ++kk) {
            float4 a0 = *reinterpret_cast<const float4*>(&As[kk][row0]);
            float4 a1 = *reinterpret_cast<const float4*>(&As[kk][row0 + 4]);
            float4 b0 = *reinterpret_cast<const float4*>(&Bs[kk][col0]);
            float4 b1 = *reinterpret_cast<const float4*>(&Bs[kk][col0 + 4]);
            float2 bp0 = make_float2(b0.x, b0.y);
            float2 bp1 = make_float2(b0.z, b0.w);
            float2 bp2 = make_float2(b1.x, b1.y);
            float2 bp3 = make_float2(b1.z, b1.w);
            float ar[8] = {a0.x, a0.y, a0.z, a0.w, a1.x, a1.y, a1.z, a1.w};
#pragma unroll
            for (int r = 0; r < 8; ++r) {
                float2 ad = make_float2(ar[r], ar[r]);
                acc[r][0] = ffma2(ad, bp0, acc[r][0]);
                acc[r][1] = ffma2(ad, bp1, acc[r][1]);
                acc[r][2] = ffma2(ad, bp2, acc[r][2]);
                acc[r][3] = ffma2(ad, bp3, acc[r][3]);
            }
        }
    };

    // prologue: tile 0
    float4 a0 = *reinterpret_cast<const float4*>(Abase0);
    float4 a1 = *reinterpret_cast<const float4*>(Abase1);
    float4 b0 = *reinterpret_cast<const float4*>(Wbase0);
    float4 b1 = *reinterpret_cast<const float4*>(Wbase1);
    sts_tiles(a0, a1, b0, b1);
    __syncthreads();

#pragma unroll 1
    for (int k0 = TK; k0 < K; k0 += TK) {
        // prefetch next tile into registers (overlaps with compute below)
        a0 = *reinterpret_cast<const float4*>(Abase0 + k0);
        a1 = *reinterpret_cast<const float4*>(Abase1 + k0);
        b0 = *reinterpret_cast<const float4*>(Wbase0 + k0);
        b1 = *reinterpret_cast<const float4*>(Wbase1 + k0);
        compute_tile();
        __syncthreads();
        sts_tiles(a0, a1, b0, b1);
        __syncthreads();
    }
    compute_tile();

    float4 bi0 = *reinterpret_cast<const float4*>(bias + bn + col0);
    float4 bi1 = *reinterpret_cast<const float4*>(bias + bn + col0 + 4);
#pragma unroll
    for (int r = 0; r < 8; ++r) {
        size_t row = (size_t)(bm + row0 + r);
        float4 o0 = make_float4(acc[r][0].x + bi0.x, acc[r][0].y + bi0.y,
                                acc[r][1].x + bi0.z, acc[r][1].y + bi0.w);
        float4 o1 = make_float4(acc[r][2].x + bi1.x, acc[r][2].y + bi1.y,
                                acc[r][3].x + bi1.z, acc[r][3].y + bi1.w);
        *reinterpret_cast<float4*>(C + row * N + bn + col0)     = o0;
        *reinterpret_cast<float4*>(C + row * N + bn + col0 + 4) = o1;
    }
}

// ---------------- persistent recurrent scan ----------------
// Grid: 128 blocks = 4 row-groups (16 batch rows) x 32 col-tiles (32 cols).
// 256 threads/block = 8 warps = 2 warps per SMSP, k-split within each chunk.
//
// h staging is CHUNKED (8 x 128 k), double-buffered in SMEM, and prefetched
// TWO chunks deep in registers (stA = commit-ready, stB = in flight):
//   chunk c: STS(stA); sync; stA=stB; LDG(c+2)->stB; FMA(c)
// LDG(c+2) gets two chunk FMA-windows (~1K cyc) to cover L2 latency instead
// of one (~512 cyc) -> removes the per-chunk exposed-latency suspected in the
// R10 scan gap. Buffer-hazard timing is unchanged from depth-1 (sync(c+1)
// fences FMA(c) before STS(c+2) rewrites that buffer).
#define SCAN_BLOCKS 128
#define SCAN_THREADS 256
#define CHUNK 128                         // k per chunk
#define NCHUNK (HH / CHUNK)               // 8
#define CP (CHUNK + 4)                    // padded chunk row
#define SCAN_SMEM ((HH * 32 + 2 * 16 * CP) * (int)sizeof(float))   // 147,968 B

__global__ __launch_bounds__(SCAN_THREADS, 1)
void scan_kernel(const float* __restrict__ P,      // [B][T][H] input proj (incl. its bias)
                 const float* __restrict__ Whh,    // [H][H] row-major (out, in)
                 const float* __restrict__ bias,   // [H]
                 const float* __restrict__ hinit,  // [B][H]
                 float* __restrict__ Hst)          // [B][T][H] states out
{
    extern __shared__ float smem[];
    float* Ws = smem;                     // [HH][32] transposed W slice
    float* hs = smem + HH * 32;           // [2][16][CP] chunk double buffer

    const int tid = threadIdx.x;
    const int bc = (blockIdx.x & 31) * 32;   // column base
    const int rg = blockIdx.x >> 5;          // row group 0..3
    const int br = rg * 16;                  // batch-row base
    unsigned* barp = &g_bar[rg * 32];        // 128 B-strided counter (own L2 line)

    // One-time: load W slice transposed into SMEM (lane c spread -> conflict-free STS)
    for (int i = tid; i < 32 * (HH / 4); i += SCAN_THREADS) {
        int c = i & 31;        // 0..31
        int q = i >> 5;        // 0..255 (float4 index along K)
        float4 v = *reinterpret_cast<const float4*>(Whh + (size_t)(bc + c) * HH + q * 4);
        Ws[(q * 4 + 0) * 32 + c] = v.x;
        Ws[(q * 4 + 1) * 32 + c] = v.y;
        Ws[(q * 4 + 2) * 32 + c] = v.z;
        Ws[(q * 4 + 3) * 32 + c] = v.w;
    }

    const int kh    = tid >> 7;          // k-half group (0 or 1)
    const int wtid  = tid & 127;
    const int khoff = kh * 64;           // k offset within a chunk
    const int r_loc = wtid & 15;         // warp spans all 16 rows
    const int c_loc = (wtid >> 4) * 4;   // 2 col-groups per warp -> W broadcast
    // staging mapping: row st_r, float4 quads {st_q, st_q+16} (16 B lane stride)
    const int st_r = tid >> 4;           // 0..15
    const int st_q = tid & 15;           // 0..15
    const float4 bias4 = *reinterpret_cast<const float4*>(bias + bc + c_loc);
    __syncthreads();

    for (int t = 0; t < TT; ++t) {
        // prefetch this step's input projection early (group 0 only needs it);
        // streaming: each P address is read exactly once whole-kernel.
        size_t off = (size_t)(br + r_loc) * TT * HH + (size_t)t * HH + bc + c_loc;
        float4 pv = make_float4(0.f, 0.f, 0.f, 0.f);
        if (tid < 128) pv = __ldcs(reinterpret_cast<const float4*>(P + off));

        const float* hbase;
        size_t rstride;
        if (t == 0) { hbase = hinit + (size_t)br * HH;                           rstride = HH; }
        else        { hbase = Hst + (size_t)br * TT * HH + (size_t)(t - 1) * HH; rstride = (size_t)TT * HH; }
        const float* hrowg = hbase + (size_t)st_r * rstride;   // this thread's staging row

        // prologue: chunk 0 -> stA, chunk 1 -> stB
        float4 stA[2], stB[2];
#pragma unroll
        for (int j = 0; j < 2; ++j)
            stA[j] = __ldcg(reinterpret_cast<const float4*>(hrowg) + st_q + j * 16);
#pragma unroll
        for (int j = 0; j < 2; ++j)
            stB[j] = __ldcg(reinterpret_cast<const float4*>(hrowg + CHUNK) + st_q + j * 16);

        float2 acc[4][2];
#pragma unroll
        for (int j = 0; j < 4; ++j) { acc[j][0] = make_float2(0.f, 0.f); acc[j][1] = make_float2(0.f, 0.f); }

#pragma unroll
        for (int c = 0; c < NCHUNK; ++c) {
            // commit stA (chunk c) to its buffer (conflict-free STS.128)
            float* buf = hs + (c & 1) * (16 * CP);
#pragma unroll
            for (int j = 0; j < 2; ++j)
                *reinterpret_cast<float4*>(&buf[st_r * CP + (st_q + j * 16) * 4]) = stA[j];
            __syncthreads();

            // rotate register sets; issue LDG for chunk c+2 (two windows of cover)
#pragma unroll
            for (int j = 0; j < 2; ++j) stA[j] = stB[j];
            if (c + 2 < NCHUNK) {
#pragma unroll
                for (int j = 0; j < 2; ++j)
                    stB[j] = __ldcg(reinterpret_cast<const float4*>(hrowg + (c + 2) * CHUNK) + st_q + j * 16);
            }

            // FMA over this group's 64-k subrange of the chunk
            const float* hrow = &buf[r_loc * CP + khoff];
            const float* wb = Ws + (c * CHUNK + khoff) * 32;
#pragma unroll 4
            for (int k = 0; k < 64; k += 4) {
                float4 hv = *reinterpret_cast<const float4*>(&hrow[k]);
                float hvr[4] = {hv.x, hv.y, hv.z, hv.w};
#pragma unroll
                for (int j = 0; j < 4; ++j) {
                    float4 w = *reinterpret_cast<const float4*>(&wb[(k + j) * 32 + c_loc]);
                    float2 hd = make_float2(hvr[j], hvr[j]);
                    acc[j][0] = ffma2(hd, make_float2(w.x, w.y), acc[j][0]);
                    acc[j][1] = ffma2(hd, make_float2(w.z, w.w), acc[j][1]);
                }
            }
        }

        float s0 = (acc[0][0].x + acc[1][0].x) + (acc[2][0].x + acc[3][0].x);
        float s1 = (acc[0][0].y + acc[1][0].y) + (acc[2][0].y + acc[3][0].y);
        float s2 = (acc[0][1].x + acc[1][1].x) + (acc[2][1].x + acc[3][1].x);
        float s3 = (acc[0][1].y + acc[1][1].y) + (acc[2][1].y + acc[3][1].y);

        // cross-group reduction: group 1 writes partials, group 0 combines.
        // red region = chunk buffer 0; last FMA read buffer 1, and next step's
        // first STS to buffer 0 is behind two syncs + the grid barrier -> safe.
        float* red = hs;
        if (tid >= 128)
            *reinterpret_cast<float4*>(&red[wtid * 4]) = make_float4(s0, s1, s2, s3);
        __syncthreads();
        if (tid < 128) {
            float4 pr = *reinterpret_cast<const float4*>(&red[wtid * 4]);
            float4 ov;
            ov.x = tanhf(s0 + pr.x + pv.x + bias4.x);
            ov.y = tanhf(s1 + pr.y + pv.y + bias4.y);
            ov.z = tanhf(s2 + pr.z + pv.z + bias4.z);
            ov.w = tanhf(s3 + pr.w + pv.w + bias4.w);
            *reinterpret_cast<float4*>(Hst + off) = ov;
        }

        // ---- per-row-group barrier (32 blocks), release/acquire, pure spin ----
        __syncthreads();
        if (tid == 0) {
            asm volatile("red.release.gpu.global.add.u32 [%0], 1;"
                         :: "l"(barp) : "memory");
            unsigned target = (unsigned)(t + 1) * 32u;
            unsigned v;
            do {
                asm volatile("ld.acquire.gpu.global.u32 %0, [%1];"
                             : "=r"(v) : "l"(barp) : "memory");
            } while (v < target);
        }
        __syncthreads();
    }
}

// ---------------- launch ----------------
extern "C" void kernel_launch(void* const* d_in, const int* in_sizes, int n_in,
                              void* d_out, int out_size)
{
    (void)in_sizes; (void)n_in; (void)out_size;
    const float* emb    = (const float*)d_in[0];   // (B,T,E)
    const float* h0     = (const float*)d_in[1];   // (L,B,H)
    const float* W_ih0  = (const float*)d_in[2];   // (H,E)
    const float* b_ih0  = (const float*)d_in[3];
    const float* W_ih1  = (const float*)d_in[4];   // (H,H)
    const float* b_ih1  = (const float*)d_in[5];
    const float* W_hh0  = (const float*)d_in[6];   // (H,H)
    const float* b_hh0  = (const float*)d_in[7];
    const float* W_hh1  = (const float*)d_in[8];   // (H,H)
    const float* b_hh1  = (const float*)d_in[9];
    const float* W_out  = (const float*)d_in[10];  // (O,H)
    const float* b_out  = (const float*)d_in[11];
    float* out = (float*)d_out;                    // (B,T,O)

    float *buf0, *buf1;
    cudaGetSymbolAddress((void**)&buf0, g_buf0);
    cudaGetSymbolAddress((void**)&buf1, g_buf1);

    cudaFuncSetAttribute(scan_kernel, cudaFuncAttributeMaxDynamicSharedMemorySize, SCAN_SMEM);

    // 1. XP = emb @ W_ih0^T + b_ih0   (row b*T+t matches (B,T,H) layout)
    gemm_bias_kernel<<<dim3(HH / TN, MROWS / TM), 256>>>(emb, W_ih0, b_ih0, buf0, MROWS, HH, EE);

    // 2. layer-0 scan: buf1 = H0_all
    reset_barrier_kernel<<<1, 1>>>();
    scan_kernel<<<SCAN_BLOCKS, SCAN_THREADS, SCAN_SMEM>>>(buf0, W_hh0, b_hh0, h0, buf1);

    // 3. YP = H0_all @ W_ih1^T + b_ih1  (overwrite buf0)
    gemm_bias_kernel<<<dim3(HH / TN, MROWS / TM), 256>>>(buf1, W_ih1, b_ih1, buf0, MROWS, HH, HH);

    // 4. layer-1 scan: buf1 = H1_all (overwrite H0_all)
    reset_barrier_kernel<<<1, 1>>>();
    scan_kernel<<<SCAN_BLOCKS, SCAN_THREADS, SCAN_SMEM>>>(buf0, W_hh1, b_hh1, h0 + BB * HH, buf1);

    // 5. out = H1_all @ W_out^T + b_out   (row b*T+t matches (B,T,O) layout)
    gemm_bias_kernel<<<dim3(OO / TN, MROWS / TM), 256>>>(buf1, W_out, b_out, out, MROWS, OO, HH);
}